// round 7
// baseline (speedup 1.0000x reference)
#include <cuda_runtime.h>

// Problem constants (fixed by the reference)
#define SEQ   1024
#define BSZ   16
#define DIM   1024
#define SIDE  32
#define BD    (BSZ * DIM)      // floats between consecutive seq positions

#define DPB   8                // d-channels per block = warps per block
#define IPB   4                // images (batch entries) per block / per warp
#define RCH   4                // rows staged per chunk
#define NCH   (SIDE / RCH)     // 8 chunks
#define LDD   132              // 4 images * 32 cols + 4 pad floats

// out[s,b,d] = silu( conv2d_causal(x, K_d)[s] + x[s,b,d]*omega[d] )
// via running the 2-state 2D SSM recurrence directly on x.
// Warp = one channel d, 4 images; lane (ib=lane>>3, g=lane&7) owns cols 4g..4g+3.
// Chunks of 4 rows are software-pipelined: next chunk's gmem loads are issued
// into registers before computing the current chunk (double-buffered smem).
// Reg-dieted to 64 regs (4 blocks/SM): coefficient powers rematerialized in-loop.
__global__ __launch_bounds__(256, 4) void ssm2d_kernel(
    const float* __restrict__ x,
    const float* __restrict__ A1, const float* __restrict__ A2,
    const float* __restrict__ B1, const float* __restrict__ B2,
    const float* __restrict__ C1, const float* __restrict__ C2,
    const float* __restrict__ omega,
    float* __restrict__ out)
{
    __shared__ __align__(16) float buf[2][RCH][DPB][LDD];

    const int tid  = threadIdx.x;
    const int w    = tid >> 5;          // warp id == channel within block
    const int lane = tid & 31;
    const int ib   = lane >> 3;         // image index within warp (0..3)
    const int g    = lane & 7;          // column-group (cols 4g..4g+3)

    const int d0 = blockIdx.x * DPB;
    const int b0 = blockIdx.y * IPB;
    const int d  = d0 + w;

    // loader/writeback role: float2 over channels (32B-sector exact)
    const int lch2 = tid & 3;           // channel pair -> ch = 2*lch2
    const int lcol = (tid >> 2) & 31;   // column
    const int lsub = tid >> 7;          // image half: images 2*lsub, 2*lsub+1
    const int ch   = 2 * lch2;

    const float SC = 0.70710678118654752440f;  // sqrt(1/2)

    // per-channel parameters (broadcast within warp)
    float a1[2], a2[2], b1[2], b2[2], c1[2], c2[2];
#pragma unroll
    for (int k = 0; k < 2; ++k) {
        a1[k] = 0.5f / (1.f + __expf(-A1[d * 2 + k]));
        a2[k] = 0.5f / (1.f + __expf(-A2[d * 2 + k]));
        b1[k] = 0.5f / (1.f + __expf(-B1[d * 2 + k]));
        b2[k] = 0.5f / (1.f + __expf(-B2[d * 2 + k]));
        c1[k] = C1[d * 2 + k] * SC;
        c2[k] = C2[d * 2 + k] * SC;
    }
    const float om = omega[d];

    // only p2, p4 stay live; p3/p8/p16 are rematerialized per row (reg diet)
    float p2[2], p4[2];
#pragma unroll
    for (int k = 0; k < 2; ++k) {
        p2[k] = a1[k] * a1[k];
        p4[k] = p2[k] * p2[k];
    }

    // previous-row state for this lane's 4 columns, both components
    float h[2][4] = {{0.f,0.f,0.f,0.f},{0.f,0.f,0.f,0.f}};
    float v[2][4] = {{0.f,0.f,0.f,0.f},{0.f,0.f,0.f,0.f}};

    // ---- prologue: load + stage chunk 0 ----
    float2 R[RCH][2];
#pragma unroll
    for (int r = 0; r < RCH; ++r)
#pragma unroll
        for (int it = 0; it < 2; ++it) {
            const int i = 2 * lsub + it;
            const int s = r * SIDE + lcol;
            R[r][it] = *(const float2*)&x[s * BD + (b0 + i) * DIM + d0 + ch];
        }
#pragma unroll
    for (int r = 0; r < RCH; ++r)
#pragma unroll
        for (int it = 0; it < 2; ++it) {
            const int i = 2 * lsub + it;
            buf[0][r][ch    ][i * SIDE + lcol] = R[r][it].x;
            buf[0][r][ch + 1][i * SIDE + lcol] = R[r][it].y;
        }

    for (int c = 0; c < NCH; ++c) {
        const int p = c & 1;
        __syncthreads();   // staged chunk c visible; prior writeback reads done

        // issue next chunk's loads early (latency hidden under compute)
        if (c + 1 < NCH) {
#pragma unroll
            for (int r = 0; r < RCH; ++r)
#pragma unroll
                for (int it = 0; it < 2; ++it) {
                    const int i = 2 * lsub + it;
                    const int s = ((c + 1) * RCH + r) * SIDE + lcol;
                    R[r][it] = *(const float2*)&x[s * BD + (b0 + i) * DIM + d0 + ch];
                }
        }

        // ---- recurrence on chunk c ----
#pragma unroll
        for (int r = 0; r < RCH; ++r) {
            const float4 xv = *(const float4*)&buf[p][r][w][ib * SIDE + 4 * g];
            const float xs[4] = {xv.x, xv.y, xv.z, xv.w};

            float o0 = om * xs[0], o1 = om * xs[1];
            float o2 = om * xs[2], o3 = om * xs[3];

#pragma unroll
            for (int k = 0; k < 2; ++k) {
                // vertical update (elementwise per column)
                float v0 = fmaf(a2[k], h[k][0], fmaf(a1[k], v[k][0], b2[k] * xs[0]));
                float v1 = fmaf(a2[k], h[k][1], fmaf(a1[k], v[k][1], b2[k] * xs[1]));
                float v2 = fmaf(a2[k], h[k][2], fmaf(a1[k], v[k][2], b2[k] * xs[2]));
                float v3 = fmaf(a2[k], h[k][3], fmaf(a1[k], v[k][3], b2[k] * xs[3]));

                // v of the column left of this lane's chunk
                float vl = __shfl_up_sync(0xffffffffu, v3, 1);
                if (g == 0) vl = 0.f;

                // local serial prefix of h-drive
                float Y0 = fmaf(a2[k], vl, b1[k] * xs[0]);
                float Y1 = fmaf(a1[k], Y0, fmaf(a2[k], v0, b1[k] * xs[1]));
                float Y2 = fmaf(a1[k], Y1, fmaf(a2[k], v1, b1[k] * xs[2]));
                float Y3 = fmaf(a1[k], Y2, fmaf(a2[k], v2, b1[k] * xs[3]));

                // rematerialize higher powers (cheap; keeps live set small)
                const float p8  = p4[k] * p4[k];
                const float p16 = p8 * p8;
                const float p3  = p2[k] * a1[k];

                // 3-step scan over 8-lane group, coefficient a1^4
                float S = Y3, t;
                t = __shfl_up_sync(0xffffffffu, S, 1);
                if (g >= 1) S = fmaf(p4[k], t, S);
                t = __shfl_up_sync(0xffffffffu, S, 2);
                if (g >= 2) S = fmaf(p8, t, S);
                t = __shfl_up_sync(0xffffffffu, S, 4);
                if (g >= 4) S = fmaf(p16, t, S);

                // incoming h at the left chunk boundary
                float hin = __shfl_up_sync(0xffffffffu, S, 1);
                if (g == 0) hin = 0.f;

                // reconstruct h for the 4 owned columns
                float h0 = fmaf(a1[k], hin, Y0);
                float h1 = fmaf(p2[k], hin, Y1);
                float h2 = fmaf(p3,    hin, Y2);
                float h3 = fmaf(p4[k], hin, Y3);

                h[k][0] = h0; h[k][1] = h1; h[k][2] = h2; h[k][3] = h3;
                v[k][0] = v0; v[k][1] = v1; v[k][2] = v2; v[k][3] = v3;

                o0 = fmaf(c1[k], h0, fmaf(c2[k], v0, o0));
                o1 = fmaf(c1[k], h1, fmaf(c2[k], v1, o1));
                o2 = fmaf(c1[k], h2, fmaf(c2[k], v2, o2));
                o3 = fmaf(c1[k], h3, fmaf(c2[k], v3, o3));
            }

            // silu + stage output in place (same slot this thread read)
            float4 ov;
            ov.x = o0 * __fdividef(1.f, 1.f + __expf(-o0));
            ov.y = o1 * __fdividef(1.f, 1.f + __expf(-o1));
            ov.z = o2 * __fdividef(1.f, 1.f + __expf(-o2));
            ov.w = o3 * __fdividef(1.f, 1.f + __expf(-o3));
            *(float4*)&buf[p][r][w][ib * SIDE + 4 * g] = ov;
        }

        __syncthreads();   // silu results visible

        // stage next chunk into the other buffer (data arrived during compute)
        if (c + 1 < NCH) {
#pragma unroll
            for (int r = 0; r < RCH; ++r)
#pragma unroll
                for (int it = 0; it < 2; ++it) {
                    const int i = 2 * lsub + it;
                    buf[p ^ 1][r][ch    ][i * SIDE + lcol] = R[r][it].x;
                    buf[p ^ 1][r][ch + 1][i * SIDE + lcol] = R[r][it].y;
                }
        }

        // ---- write back chunk c (float2 over channels, 32B sectors) ----
#pragma unroll
        for (int r = 0; r < RCH; ++r)
#pragma unroll
            for (int it = 0; it < 2; ++it) {
                const int i = 2 * lsub + it;
                const int s = (c * RCH + r) * SIDE + lcol;
                float2 o2v;
                o2v.x = buf[p][r][ch    ][i * SIDE + lcol];
                o2v.y = buf[p][r][ch + 1][i * SIDE + lcol];
                *(float2*)&out[s * BD + (b0 + i) * DIM + d0 + ch] = o2v;
            }
    }
}

extern "C" void kernel_launch(void* const* d_in, const int* in_sizes, int n_in,
                              void* d_out, int out_size)
{
    const float* x     = (const float*)d_in[0];
    const float* A1    = (const float*)d_in[1];
    const float* A2    = (const float*)d_in[2];
    const float* B1    = (const float*)d_in[3];
    const float* B2    = (const float*)d_in[4];
    const float* C1    = (const float*)d_in[5];
    const float* C2    = (const float*)d_in[6];
    const float* omega = (const float*)d_in[7];
    float* out = (float*)d_out;

    dim3 block(DPB * 32);                 // 256 threads
    dim3 grid(DIM / DPB, BSZ / IPB);      // 128 x 4 = 512 blocks
    ssm2d_kernel<<<grid, block>>>(x, A1, A2, B1, B2, C1, C2, omega, out);
}

// round 8
// speedup vs baseline: 1.0333x; 1.0333x over previous
#include <cuda_runtime.h>

// Problem constants (fixed by the reference)
#define SEQ   1024
#define BSZ   16
#define DIM   1024
#define SIDE  32
#define BD    (BSZ * DIM)      // floats between consecutive seq positions

#define DPB   8                // d-channels per block = warps per block
#define IPB   4                // images (batch entries) per block / per warp
#define RCH   4                // rows staged per chunk
#define NCH   (SIDE / RCH)     // 8 chunks
#define LDD   132              // 4 images * 32 cols + 4 pad floats

// out[s,b,d] = silu( conv2d_causal(x, K_d)[s] + x[s,b,d]*omega[d] )
// via running the 2-state 2D SSM recurrence directly on x.
// Warp = one channel d, 4 images; lane (ib=lane>>3, g=lane&7) owns cols 4g..4g+3.
// Single-barrier software pipeline: per iteration -> sync; LDG c+1; writeback
// c-1; compute c; stage c+1. Writeback-read and stage-write hit the same smem
// slots from the same thread (program-order safe), so one barrier suffices.
__global__ __launch_bounds__(256, 3) void ssm2d_kernel(
    const float* __restrict__ x,
    const float* __restrict__ A1, const float* __restrict__ A2,
    const float* __restrict__ B1, const float* __restrict__ B2,
    const float* __restrict__ C1, const float* __restrict__ C2,
    const float* __restrict__ omega,
    float* __restrict__ out)
{
    __shared__ __align__(16) float buf[2][RCH][DPB][LDD];

    const int tid  = threadIdx.x;
    const int w    = tid >> 5;          // warp id == channel within block
    const int lane = tid & 31;
    const int ib   = lane >> 3;         // image index within warp (0..3)
    const int g    = lane & 7;          // column-group (cols 4g..4g+3)

    const int d0 = blockIdx.x * DPB;
    const int b0 = blockIdx.y * IPB;
    const int d  = d0 + w;

    // loader/writeback role: float2 over channels (32B-sector exact)
    const int lch2 = tid & 3;           // channel pair -> ch = 2*lch2
    const int lcol = (tid >> 2) & 31;   // column
    const int lsub = tid >> 7;          // image half: images 2*lsub, 2*lsub+1
    const int ch   = 2 * lch2;

    const float SC = 0.70710678118654752440f;  // sqrt(1/2)

    // per-channel parameters (broadcast within warp)
    float a1[2], a2[2], b1[2], b2[2], c1[2], c2[2];
#pragma unroll
    for (int k = 0; k < 2; ++k) {
        a1[k] = 0.5f / (1.f + __expf(-A1[d * 2 + k]));
        a2[k] = 0.5f / (1.f + __expf(-A2[d * 2 + k]));
        b1[k] = 0.5f / (1.f + __expf(-B1[d * 2 + k]));
        b2[k] = 0.5f / (1.f + __expf(-B2[d * 2 + k]));
        c1[k] = C1[d * 2 + k] * SC;
        c2[k] = C2[d * 2 + k] * SC;
    }
    const float om = omega[d];

    // precomputed coefficient powers for scan & reconstruction
    float p2[2], p3[2], p4[2], p8[2], p16[2];
#pragma unroll
    for (int k = 0; k < 2; ++k) {
        p2[k]  = a1[k] * a1[k];
        p3[k]  = p2[k] * a1[k];
        p4[k]  = p2[k] * p2[k];
        p8[k]  = p4[k] * p4[k];
        p16[k] = p8[k] * p8[k];
    }

    // previous-row state for this lane's 4 columns, both components
    float h[2][4] = {{0.f,0.f,0.f,0.f},{0.f,0.f,0.f,0.f}};
    float v[2][4] = {{0.f,0.f,0.f,0.f},{0.f,0.f,0.f,0.f}};

    const int gstr = b0 * DIM + d0 + ch;   // gmem base offset (per loader thread)

    // ---- prologue: load + stage chunk 0 into buf[0] ----
    float2 R[RCH][2];
#pragma unroll
    for (int r = 0; r < RCH; ++r)
#pragma unroll
        for (int it = 0; it < 2; ++it) {
            const int i = 2 * lsub + it;
            const int s = r * SIDE + lcol;
            R[r][it] = *(const float2*)&x[s * BD + i * DIM + gstr];
        }
#pragma unroll
    for (int r = 0; r < RCH; ++r)
#pragma unroll
        for (int it = 0; it < 2; ++it) {
            const int i = 2 * lsub + it;
            buf[0][r][ch    ][i * SIDE + lcol] = R[r][it].x;
            buf[0][r][ch + 1][i * SIDE + lcol] = R[r][it].y;
        }

    for (int c = 0; c < NCH; ++c) {
        const int p = c & 1;
        __syncthreads();   // stage(c) and silu(c-1) visible block-wide

        // (1) issue next chunk's loads (latency hidden under writeback+compute)
        if (c + 1 < NCH) {
#pragma unroll
            for (int r = 0; r < RCH; ++r)
#pragma unroll
                for (int it = 0; it < 2; ++it) {
                    const int i = 2 * lsub + it;
                    const int s = ((c + 1) * RCH + r) * SIDE + lcol;
                    R[r][it] = *(const float2*)&x[s * BD + i * DIM + gstr];
                }
        }

        // (2) write back chunk c-1 (reads buf[p^1]; STGs drain under compute)
        if (c > 0) {
#pragma unroll
            for (int r = 0; r < RCH; ++r)
#pragma unroll
                for (int it = 0; it < 2; ++it) {
                    const int i = 2 * lsub + it;
                    const int s = ((c - 1) * RCH + r) * SIDE + lcol;
                    float2 o2v;
                    o2v.x = buf[p ^ 1][r][ch    ][i * SIDE + lcol];
                    o2v.y = buf[p ^ 1][r][ch + 1][i * SIDE + lcol];
                    *(float2*)&out[s * BD + i * DIM + gstr] = o2v;
                }
        }

        // (3) recurrence on chunk c (reads/writes buf[p] only)
#pragma unroll
        for (int r = 0; r < RCH; ++r) {
            const float4 xv = *(const float4*)&buf[p][r][w][ib * SIDE + 4 * g];
            const float xs[4] = {xv.x, xv.y, xv.z, xv.w};

            float o0 = om * xs[0], o1 = om * xs[1];
            float o2 = om * xs[2], o3 = om * xs[3];

#pragma unroll
            for (int k = 0; k < 2; ++k) {
                // vertical update (elementwise per column)
                float v0 = fmaf(a2[k], h[k][0], fmaf(a1[k], v[k][0], b2[k] * xs[0]));
                float v1 = fmaf(a2[k], h[k][1], fmaf(a1[k], v[k][1], b2[k] * xs[1]));
                float v2 = fmaf(a2[k], h[k][2], fmaf(a1[k], v[k][2], b2[k] * xs[2]));
                float v3 = fmaf(a2[k], h[k][3], fmaf(a1[k], v[k][3], b2[k] * xs[3]));

                // v of the column left of this lane's chunk
                float vl = __shfl_up_sync(0xffffffffu, v3, 1);
                if (g == 0) vl = 0.f;

                // local serial prefix of h-drive
                float Y0 = fmaf(a2[k], vl, b1[k] * xs[0]);
                float Y1 = fmaf(a1[k], Y0, fmaf(a2[k], v0, b1[k] * xs[1]));
                float Y2 = fmaf(a1[k], Y1, fmaf(a2[k], v1, b1[k] * xs[2]));
                float Y3 = fmaf(a1[k], Y2, fmaf(a2[k], v2, b1[k] * xs[3]));

                // 3-step scan over 8-lane group, coefficient a1^4
                float S = Y3, t;
                t = __shfl_up_sync(0xffffffffu, S, 1);
                if (g >= 1) S = fmaf(p4[k], t, S);
                t = __shfl_up_sync(0xffffffffu, S, 2);
                if (g >= 2) S = fmaf(p8[k], t, S);
                t = __shfl_up_sync(0xffffffffu, S, 4);
                if (g >= 4) S = fmaf(p16[k], t, S);

                // incoming h at the left chunk boundary
                float hin = __shfl_up_sync(0xffffffffu, S, 1);
                if (g == 0) hin = 0.f;

                // reconstruct h for the 4 owned columns
                float h0 = fmaf(a1[k], hin, Y0);
                float h1 = fmaf(p2[k], hin, Y1);
                float h2 = fmaf(p3[k], hin, Y2);
                float h3 = fmaf(p4[k], hin, Y3);

                h[k][0] = h0; h[k][1] = h1; h[k][2] = h2; h[k][3] = h3;
                v[k][0] = v0; v[k][1] = v1; v[k][2] = v2; v[k][3] = v3;

                o0 = fmaf(c1[k], h0, fmaf(c2[k], v0, o0));
                o1 = fmaf(c1[k], h1, fmaf(c2[k], v1, o1));
                o2 = fmaf(c1[k], h2, fmaf(c2[k], v2, o2));
                o3 = fmaf(c1[k], h3, fmaf(c2[k], v3, o3));
            }

            // silu + stage output in place (same slot this thread read)
            float4 ov;
            ov.x = o0 * __fdividef(1.f, 1.f + __expf(-o0));
            ov.y = o1 * __fdividef(1.f, 1.f + __expf(-o1));
            ov.z = o2 * __fdividef(1.f, 1.f + __expf(-o2));
            ov.w = o3 * __fdividef(1.f, 1.f + __expf(-o3));
            *(float4*)&buf[p][r][w][ib * SIDE + 4 * g] = ov;
        }

        // (4) stage chunk c+1 into buf[p^1] — same slots this thread read in (2),
        //     same-thread program order makes it safe without a barrier
        if (c + 1 < NCH) {
#pragma unroll
            for (int r = 0; r < RCH; ++r)
#pragma unroll
                for (int it = 0; it < 2; ++it) {
                    const int i = 2 * lsub + it;
                    buf[p ^ 1][r][ch    ][i * SIDE + lcol] = R[r][it].x;
                    buf[p ^ 1][r][ch + 1][i * SIDE + lcol] = R[r][it].y;
                }
        }
    }

    // ---- epilogue: write back final chunk (NCH-1, lives in buf[(NCH-1)&1]) ----
    __syncthreads();
    {
        const int p = (NCH - 1) & 1;
#pragma unroll
        for (int r = 0; r < RCH; ++r)
#pragma unroll
            for (int it = 0; it < 2; ++it) {
                const int i = 2 * lsub + it;
                const int s = ((NCH - 1) * RCH + r) * SIDE + lcol;
                float2 o2v;
                o2v.x = buf[p][r][ch    ][i * SIDE + lcol];
                o2v.y = buf[p][r][ch + 1][i * SIDE + lcol];
                *(float2*)&out[s * BD + i * DIM + gstr] = o2v;
            }
    }
}

extern "C" void kernel_launch(void* const* d_in, const int* in_sizes, int n_in,
                              void* d_out, int out_size)
{
    const float* x     = (const float*)d_in[0];
    const float* A1    = (const float*)d_in[1];
    const float* A2    = (const float*)d_in[2];
    const float* B1    = (const float*)d_in[3];
    const float* B2    = (const float*)d_in[4];
    const float* C1    = (const float*)d_in[5];
    const float* C2    = (const float*)d_in[6];
    const float* omega = (const float*)d_in[7];
    float* out = (float*)d_out;

    dim3 block(DPB * 32);                 // 256 threads
    dim3 grid(DIM / DPB, BSZ / IPB);      // 128 x 4 = 512 blocks
    ssm2d_kernel<<<grid, block>>>(x, A1, A2, B1, B2, C1, C2, omega, out);
}

// round 9
// speedup vs baseline: 1.1065x; 1.0708x over previous
#include <cuda_runtime.h>
#include <cstdint>

// Problem constants (fixed by the reference)
#define SEQ   1024
#define BSZ   16
#define DIM   1024
#define SIDE  32
#define BD    (BSZ * DIM)

#define DPB   32               // channels per block = warps per block
#define IPB   4                // images per block (all handled by every warp)
#define RCH   4                // rows per chunk
#define NCH   (SIDE / RCH)     // 8 chunks
#define SCs   33               // smem col stride (floats), == 1 mod 32
#define SIs   1057             // smem image stride = 32*33+1, == 1 mod 32
#define SLOT  (IPB * SIs)      // 4228 floats per (buffer,row) slot
#define SMEM_FLOATS (2 * RCH * SLOT)
#define SMEM_BYTES  (SMEM_FLOATS * 4)   // 135296 B

// 4-byte async copy gmem->smem (scatter-transpose with zero register cost)
__device__ __forceinline__ void cpa4(uint32_t dst, const float* src) {
    asm volatile("cp.async.ca.shared.global [%0], [%1], 4;" :: "r"(dst), "l"(src));
}

// out[s,b,d] = silu( conv2d_causal(x, K_d)[s] + x[s,b,d]*omega[d] )
// via running the 2-state 2D SSM recurrence directly on x.
// Block: 32 channels x 4 images. Warp = one channel, 4 images; lane
// (ib=lane>>3, g=lane&7) owns cols 4g..4g+3 of image ib.
// IO role: warp = one column, lane = channel -> every gmem warp access is one
// full 128B line. cp.async scatters into padded smem (no prefetch registers).
__global__ __launch_bounds__(1024, 1) void ssm2d_kernel(
    const float* __restrict__ x,
    const float* __restrict__ A1, const float* __restrict__ A2,
    const float* __restrict__ B1, const float* __restrict__ B2,
    const float* __restrict__ C1, const float* __restrict__ C2,
    const float* __restrict__ omega,
    float* __restrict__ out)
{
    extern __shared__ float buf[];
    const uint32_t sb = (uint32_t)__cvta_generic_to_shared(buf);

    const int tid  = threadIdx.x;
    const int w    = tid >> 5;        // warp id: compute channel / io column
    const int lane = tid & 31;
    const int ib   = lane >> 3;       // image (compute role)
    const int g    = lane & 7;        // column group (compute role)

    const int d0 = blockIdx.x * DPB;
    const int b0 = blockIdx.y * IPB;
    const int d  = d0 + w;

    // io role constants: gmem off = s*BD + (b0+im)*DIM + d0 + lane, s = row*32 + w
    const int gio = w * BD + b0 * DIM + d0 + lane;   // + r*SIDE*BD + im*DIM + c*RCH*SIDE*BD
    // io smem idx = slot*SLOT + im*SIs + w*SCs + lane
    const int sio = w * SCs + lane;

    const float SC = 0.70710678118654752440f;  // sqrt(1/2)

    float a1[2], a2[2], b1[2], b2[2], c1[2], c2[2];
#pragma unroll
    for (int k = 0; k < 2; ++k) {
        a1[k] = 0.5f / (1.f + __expf(-A1[d * 2 + k]));
        a2[k] = 0.5f / (1.f + __expf(-A2[d * 2 + k]));
        b1[k] = 0.5f / (1.f + __expf(-B1[d * 2 + k]));
        b2[k] = 0.5f / (1.f + __expf(-B2[d * 2 + k]));
        c1[k] = C1[d * 2 + k] * SC;
        c2[k] = C2[d * 2 + k] * SC;
    }
    const float om = omega[d];

    // keep only p2, p4 live; p3/p8/p16 rematerialized per row
    float p2[2], p4[2];
#pragma unroll
    for (int k = 0; k < 2; ++k) { p2[k] = a1[k] * a1[k]; p4[k] = p2[k] * p2[k]; }

    // previous-row state for this lane's 4 columns, both components
    float h[2][4] = {{0.f,0.f,0.f,0.f},{0.f,0.f,0.f,0.f}};
    float v[2][4] = {{0.f,0.f,0.f,0.f},{0.f,0.f,0.f,0.f}};

    const int cbase = ib * SIs + w;   // compute smem base (+ slot, + (4g+cc)*SCs)

    // ---- prologue: async-load chunk 0 into buffer 0 ----
#pragma unroll
    for (int t = 0; t < RCH * IPB; ++t) {
        const int r = t >> 2, im = t & 3;
        cpa4(sb + 4u * (r * SLOT + im * SIs + sio),
             x + gio + r * (SIDE * BD) + im * DIM);
    }
    asm volatile("cp.async.commit_group;" ::: "memory");

    for (int c = 0; c < NCH; ++c) {
        const int p = c & 1;
        asm volatile("cp.async.wait_group 0;" ::: "memory");  // chunk c arrived
        __syncthreads();   // all async writes + silu(c-1) visible block-wide

        // (1) write back chunk c-1 from buf[p^1] (gather scalar -> 128B STG)
        if (c > 0) {
            const int gwb = gio + (c - 1) * (RCH * SIDE * BD);
#pragma unroll
            for (int t = 0; t < RCH * IPB; ++t) {
                const int r = t >> 2, im = t & 3;
                const float val = buf[((p ^ 1) * RCH + r) * SLOT + im * SIs + sio];
                out[gwb + r * (SIDE * BD) + im * DIM] = val;
            }
        }

        // (2) async-load chunk c+1 into buf[p^1] (same slots this thread just
        //     read in (1); copies land >> later, same-thread order is safe)
        if (c + 1 < NCH) {
            const int gld = gio + (c + 1) * (RCH * SIDE * BD);
#pragma unroll
            for (int t = 0; t < RCH * IPB; ++t) {
                const int r = t >> 2, im = t & 3;
                cpa4(sb + 4u * (((p ^ 1) * RCH + r) * SLOT + im * SIs + sio),
                     x + gld + r * (SIDE * BD) + im * DIM);
            }
            asm volatile("cp.async.commit_group;" ::: "memory");
        }

        // (3) recurrence on chunk c (reads/writes buf[p] only)
#pragma unroll
        for (int r = 0; r < RCH; ++r) {
            const int base = (p * RCH + r) * SLOT + cbase;
            float xs[4];
#pragma unroll
            for (int cc = 0; cc < 4; ++cc) xs[cc] = buf[base + (4 * g + cc) * SCs];

            float o0 = om * xs[0], o1 = om * xs[1];
            float o2 = om * xs[2], o3 = om * xs[3];

#pragma unroll
            for (int k = 0; k < 2; ++k) {
                // vertical update (elementwise per column)
                float v0 = fmaf(a2[k], h[k][0], fmaf(a1[k], v[k][0], b2[k] * xs[0]));
                float v1 = fmaf(a2[k], h[k][1], fmaf(a1[k], v[k][1], b2[k] * xs[1]));
                float v2 = fmaf(a2[k], h[k][2], fmaf(a1[k], v[k][2], b2[k] * xs[2]));
                float v3 = fmaf(a2[k], h[k][3], fmaf(a1[k], v[k][3], b2[k] * xs[3]));

                // v of the column left of this lane's chunk
                float vl = __shfl_up_sync(0xffffffffu, v3, 1);
                if (g == 0) vl = 0.f;

                // local serial prefix of h-drive
                float Y0 = fmaf(a2[k], vl, b1[k] * xs[0]);
                float Y1 = fmaf(a1[k], Y0, fmaf(a2[k], v0, b1[k] * xs[1]));
                float Y2 = fmaf(a1[k], Y1, fmaf(a2[k], v1, b1[k] * xs[2]));
                float Y3 = fmaf(a1[k], Y2, fmaf(a2[k], v2, b1[k] * xs[3]));

                // rematerialized coefficient powers
                const float p8  = p4[k] * p4[k];
                const float p16 = p8 * p8;
                const float p3  = p2[k] * a1[k];

                // 3-step scan over 8-lane group, coefficient a1^4
                float S = Y3, t;
                t = __shfl_up_sync(0xffffffffu, S, 1);
                if (g >= 1) S = fmaf(p4[k], t, S);
                t = __shfl_up_sync(0xffffffffu, S, 2);
                if (g >= 2) S = fmaf(p8, t, S);
                t = __shfl_up_sync(0xffffffffu, S, 4);
                if (g >= 4) S = fmaf(p16, t, S);

                // incoming h at the left chunk boundary
                float hin = __shfl_up_sync(0xffffffffu, S, 1);
                if (g == 0) hin = 0.f;

                // reconstruct h for the 4 owned columns
                float h0 = fmaf(a1[k], hin, Y0);
                float h1 = fmaf(p2[k], hin, Y1);
                float h2 = fmaf(p3,    hin, Y2);
                float h3 = fmaf(p4[k], hin, Y3);

                h[k][0] = h0; h[k][1] = h1; h[k][2] = h2; h[k][3] = h3;
                v[k][0] = v0; v[k][1] = v1; v[k][2] = v2; v[k][3] = v3;

                o0 = fmaf(c1[k], h0, fmaf(c2[k], v0, o0));
                o1 = fmaf(c1[k], h1, fmaf(c2[k], v1, o1));
                o2 = fmaf(c1[k], h2, fmaf(c2[k], v2, o2));
                o3 = fmaf(c1[k], h3, fmaf(c2[k], v3, o3));
            }

            // silu + stage output in place (same slots this thread read)
            buf[base + (4 * g + 0) * SCs] = o0 * __fdividef(1.f, 1.f + __expf(-o0));
            buf[base + (4 * g + 1) * SCs] = o1 * __fdividef(1.f, 1.f + __expf(-o1));
            buf[base + (4 * g + 2) * SCs] = o2 * __fdividef(1.f, 1.f + __expf(-o2));
            buf[base + (4 * g + 3) * SCs] = o3 * __fdividef(1.f, 1.f + __expf(-o3));
        }
    }

    // ---- epilogue: write back final chunk ----
    __syncthreads();
    {
        const int q = (NCH - 1) & 1;
        const int gwb = gio + (NCH - 1) * (RCH * SIDE * BD);
#pragma unroll
        for (int t = 0; t < RCH * IPB; ++t) {
            const int r = t >> 2, im = t & 3;
            const float val = buf[(q * RCH + r) * SLOT + im * SIs + sio];
            out[gwb + r * (SIDE * BD) + im * DIM] = val;
        }
    }
}

extern "C" void kernel_launch(void* const* d_in, const int* in_sizes, int n_in,
                              void* d_out, int out_size)
{
    const float* x     = (const float*)d_in[0];
    const float* A1    = (const float*)d_in[1];
    const float* A2    = (const float*)d_in[2];
    const float* B1    = (const float*)d_in[3];
    const float* B2    = (const float*)d_in[4];
    const float* C1    = (const float*)d_in[5];
    const float* C2    = (const float*)d_in[6];
    const float* omega = (const float*)d_in[7];
    float* out = (float*)d_out;

    cudaFuncSetAttribute(ssm2d_kernel,
                         cudaFuncAttributeMaxDynamicSharedMemorySize, SMEM_BYTES);

    dim3 block(1024);
    dim3 grid(DIM / DPB, BSZ / IPB);   // 32 x 4 = 128 blocks
    ssm2d_kernel<<<grid, block, SMEM_BYTES>>>(x, A1, A2, B1, B2, C1, C2, omega, out);
}